// round 2
// baseline (speedup 1.0000x reference)
#include <cuda_runtime.h>
#include <cstddef>

#define Bz 8
#define Tz 256
#define Uz 64
#define U1 65
#define Vz 512

// Scratch (device globals: allocation inside kernel_launch is forbidden)
__device__ float g_blank[Bz * Tz * U1];   // blank log-prob per (b,t,u)
__device__ float g_emit [Bz * Tz * Uz];   // emit  log-prob per (b,t,u), u < U
__device__ float g_loss [Bz];

// ---------------------------------------------------------------------------
// Kernel 1: per-row logsumexp over V=512; extract blank + emit log-probs.
// One warp per (b,t,u) row. 272 MB streamed once -> HBM-bound.
// ---------------------------------------------------------------------------
__global__ void __launch_bounds__(256) lse_kernel(const float* __restrict__ pred,
                                                  const int* __restrict__ target)
{
    const int warp = (blockIdx.x * blockDim.x + threadIdx.x) >> 5;
    const int lane = threadIdx.x & 31;
    const int n_rows = Bz * Tz * U1;
    if (warp >= n_rows) return;

    const float* row = pred + (size_t)warp * Vz;

    // Each lane loads 16 floats as 4 x float4; each LDG.128 is a contiguous
    // 512B warp transaction.
    float4 v[4];
    float mx = -1e30f;
#pragma unroll
    for (int c = 0; c < 4; c++) {
        v[c] = *reinterpret_cast<const float4*>(row + c * 128 + lane * 4);
        mx = fmaxf(mx, fmaxf(fmaxf(v[c].x, v[c].y), fmaxf(v[c].z, v[c].w)));
    }
#pragma unroll
    for (int o = 16; o > 0; o >>= 1)
        mx = fmaxf(mx, __shfl_xor_sync(0xFFFFFFFFu, mx, o));

    float s = 0.0f;
#pragma unroll
    for (int c = 0; c < 4; c++) {
        s += __expf(v[c].x - mx) + __expf(v[c].y - mx)
           + __expf(v[c].z - mx) + __expf(v[c].w - mx);
    }
#pragma unroll
    for (int o = 16; o > 0; o >>= 1)
        s += __shfl_xor_sync(0xFFFFFFFFu, s, o);

    const float lse = mx + __logf(s);

    if (lane == 0) {
        const int b   = warp / (Tz * U1);
        const int rem = warp % (Tz * U1);
        const int t   = rem / U1;
        const int u   = rem % U1;
        g_blank[warp] = row[0] - lse;          // blank_id = 0
        if (u < Uz) {
            const int tgt = target[b * Uz + u];
            g_emit[(b * Tz + t) * Uz + u] = row[tgt] - lse;   // L1/L2 hit
        }
    }
}

// ---------------------------------------------------------------------------
// Kernel 2: alpha DP, anti-diagonal wavefront. One CTA per batch element.
// blank/emit for the batch are staged in SMEM (132 KB). Thread u owns
// column u; 319 diagonal steps, each fully parallel across u.
// ---------------------------------------------------------------------------
__global__ void __launch_bounds__(128) dp_kernel(const int* __restrict__ pred_len,
                                                 const int* __restrict__ target_len)
{
    const int b   = blockIdx.x;
    const int tid = threadIdx.x;

    extern __shared__ float sm[];
    float* s_blank = sm;                 // Tz * U1 floats
    float* s_emit  = sm + Tz * U1;       // Tz * Uz floats
    __shared__ float A[U1];              // wavefront diagonal (alpha per column)

    // Stage this batch's blank/emit from L2 into SMEM.
    const float* gb = g_blank + b * Tz * U1;
    for (int i = tid; i < Tz * U1; i += blockDim.x) s_blank[i] = gb[i];
    const float* ge = g_emit + b * Tz * Uz;
    for (int i = tid; i < Tz * Uz; i += blockDim.x) s_emit[i] = ge[i];
    __syncthreads();

    // Row 0: alpha[0][u] = cumsum of emit[0][0..u-1]  (65 serial adds, trivial)
    if (tid == 0) {
        float acc = 0.0f;
        A[0] = 0.0f;
        for (int u = 1; u <= Uz; u++) {
            acc += s_emit[u - 1];
            A[u] = acc;
        }
    }
    __syncthreads();

    const int t_last = pred_len[b] - 1;      // in [239, 255]
    const int tlen   = target_len[b];        // in [56, 64]
    float final_alpha = 0.0f;

    const int u = tid;                        // columns 0..64 active
    for (int d = 1; d <= (Tz - 1) + Uz; d++) {
        const int t = d - u;
        const bool active = (u <= Uz) && (t >= 1) && (t <= Tz - 1);
        float nv = 0.0f;
        if (active) {
            if (u == 0) {
                nv = A[0] + s_blank[(t - 1) * U1];
            } else {
                const float x = A[u]     + s_blank[(t - 1) * U1 + u];
                const float y = A[u - 1] + s_emit [t * Uz + (u - 1)];
                const float m = fmaxf(x, y);
                nv = m + __logf(1.0f + __expf(-fabsf(x - y)));
            }
        }
        __syncthreads();               // all reads of A complete
        if (active) {
            A[u] = nv;
            if (t == t_last && u == tlen) final_alpha = nv;
        }
        __syncthreads();               // writes visible before next step
    }

    if (u == tlen)
        g_loss[b] = -(final_alpha + s_blank[t_last * U1 + tlen]);
}

// ---------------------------------------------------------------------------
// Kernel 3: mean over batch -> scalar output.
// ---------------------------------------------------------------------------
__global__ void finish_kernel(float* __restrict__ out)
{
    if (threadIdx.x == 0) {
        float s = 0.0f;
#pragma unroll
        for (int i = 0; i < Bz; i++) s += g_loss[i];
        out[0] = s * (1.0f / Bz);
    }
}

extern "C" void kernel_launch(void* const* d_in, const int* in_sizes, int n_in,
                              void* d_out, int out_size)
{
    const float* pred       = (const float*)d_in[0];  // (B,T,U+1,V) fp32
    const int*   target     = (const int*)  d_in[1];  // (B,U)
    const int*   pred_len   = (const int*)  d_in[2];  // (B,)
    const int*   target_len = (const int*)  d_in[3];  // (B,)
    float*       out        = (float*)d_out;

    // Kernel 1: one warp per row, 8 warps per block.
    const int n_rows = Bz * Tz * U1;                  // 133120
    const int blocks = (n_rows + 7) / 8;              // 256 threads = 8 warps
    lse_kernel<<<blocks, 256>>>(pred, target);

    // Kernel 2: 132 KB dynamic SMEM per CTA (needs opt-in above 48 KB).
    const int smem_bytes = (Tz * U1 + Tz * Uz) * (int)sizeof(float);  // 132096
    cudaFuncSetAttribute(dp_kernel, cudaFuncAttributeMaxDynamicSharedMemorySize,
                         smem_bytes);
    dp_kernel<<<Bz, 128, smem_bytes>>>(pred_len, target_len);

    finish_kernel<<<1, 32>>>(out);
}

// round 3
// speedup vs baseline: 1.0355x; 1.0355x over previous
#include <cuda_runtime.h>
#include <cstddef>

#define Bz 8
#define Tz 256
#define Uz 64
#define U1 65
#define BSTRIDE 66   // padded blank row stride (odd delta on diagonals -> conflict-free)
#define Vz 512

// Scratch (device globals: allocation inside kernel_launch is forbidden)
__device__ float g_blank[Bz * Tz * BSTRIDE];  // blank log-prob, padded stride 66
__device__ float g_emit [Bz * Tz * Uz];       // emit  log-prob per (b,t,u), u < U
__device__ float g_loss [Bz];

// ---------------------------------------------------------------------------
// Kernel 1: per-row logsumexp over V=512; extract blank + emit log-probs.
// One warp per (b,t,u) row. 272 MB streamed once -> HBM-bound (82% of peak).
// ---------------------------------------------------------------------------
__global__ void __launch_bounds__(256) lse_kernel(const float* __restrict__ pred,
                                                  const int* __restrict__ target)
{
    const int warp = (blockIdx.x * blockDim.x + threadIdx.x) >> 5;
    const int lane = threadIdx.x & 31;
    const int n_rows = Bz * Tz * U1;
    if (warp >= n_rows) return;

    const float* row = pred + (size_t)warp * Vz;

    float4 v[4];
    float mx = -1e30f;
#pragma unroll
    for (int c = 0; c < 4; c++) {
        v[c] = __ldcs(reinterpret_cast<const float4*>(row + c * 128 + lane * 4));
        mx = fmaxf(mx, fmaxf(fmaxf(v[c].x, v[c].y), fmaxf(v[c].z, v[c].w)));
    }
#pragma unroll
    for (int o = 16; o > 0; o >>= 1)
        mx = fmaxf(mx, __shfl_xor_sync(0xFFFFFFFFu, mx, o));

    float s = 0.0f;
#pragma unroll
    for (int c = 0; c < 4; c++) {
        s += __expf(v[c].x - mx) + __expf(v[c].y - mx)
           + __expf(v[c].z - mx) + __expf(v[c].w - mx);
    }
#pragma unroll
    for (int o = 16; o > 0; o >>= 1)
        s += __shfl_xor_sync(0xFFFFFFFFu, s, o);

    const float lse = mx + __logf(s);

    if (lane == 0) {
        const int b   = warp / (Tz * U1);
        const int rem = warp % (Tz * U1);
        const int t   = rem / U1;
        const int u   = rem % U1;
        g_blank[(b * Tz + t) * BSTRIDE + u] = row[0] - lse;   // blank_id = 0
        if (u < Uz) {
            const int tgt = target[b * Uz + u];
            g_emit[(b * Tz + t) * Uz + u] = row[tgt] - lse;   // L1/L2 hit
        }
    }
}

// ---------------------------------------------------------------------------
// Kernel 2: alpha DP, anti-diagonal wavefront in a SINGLE WARP, zero barriers.
// One CTA per batch; 256 threads stage SMEM, then warp 0 runs the wavefront.
// Lane l owns columns u=l and u=l+32; lane 0 additionally owns u=64.
// All neighbor (u-1) values travel via __shfl of previous-step registers.
// ---------------------------------------------------------------------------
__device__ __forceinline__ float logadd(float x, float y)
{
    return fmaxf(x, y) + __logf(1.0f + __expf(-fabsf(x - y)));
}

__global__ void __launch_bounds__(256) dp_kernel(const int* __restrict__ pred_len,
                                                 const int* __restrict__ target_len)
{
    const int b   = blockIdx.x;
    const int tid = threadIdx.x;

    extern __shared__ float sm[];
    float* s_blank = sm;                   // Tz * BSTRIDE floats (padded)
    float* s_emit  = sm + Tz * BSTRIDE;    // Tz * Uz floats
    __shared__ float row0s[U1];

    // Stage this batch's blank/emit from L2 into SMEM (pure float4 memcpy;
    // padding was already applied by the writer).
    {
        const float4* gb = reinterpret_cast<const float4*>(g_blank + b * Tz * BSTRIDE);
        float4* sb = reinterpret_cast<float4*>(s_blank);
        for (int i = tid; i < Tz * BSTRIDE / 4; i += blockDim.x) sb[i] = gb[i];
        const float4* ge = reinterpret_cast<const float4*>(g_emit + b * Tz * Uz);
        float4* se = reinterpret_cast<float4*>(s_emit);
        for (int i = tid; i < Tz * Uz / 4; i += blockDim.x) se[i] = ge[i];
    }
    __syncthreads();

    if (tid >= 32) return;                 // only warp 0 continues; no more CTA barriers
    const int lane = tid;

    // Row 0: alpha[0][u] = cumsum of emit[0][0..u-1]  (65 cheap serial adds)
    if (lane == 0) {
        float acc = 0.0f;
        row0s[0] = 0.0f;
        for (int u = 1; u <= Uz; u++) { acc += s_emit[u - 1]; row0s[u] = acc; }
    }
    __syncwarp();

    const int t_last = pred_len[b] - 1;
    const int tlen   = target_len[b];

    float A_lo  = row0s[lane];             // alpha[.][lane]
    float A_hi  = row0s[lane + 32];        // alpha[.][lane+32]
    float A_top = row0s[Uz];               // alpha[.][64] (live on lane 0)
    float final_alpha = row0s[tlen];       // correct if t_last == 0

    const unsigned FULL = 0xFFFFFFFFu;
    const int u_hi = lane + 32;

    for (int d = 1; d <= (Tz - 1) + Uz; d++) {
        // Neighbor values from the END of step d-1 (read before any update).
        float prev_lo = __shfl_up_sync(FULL, A_lo, 1);   // A[lane-1]
        float lo31    = __shfl_sync(FULL, A_lo, 31);     // A[31]
        float prev_hi = __shfl_up_sync(FULL, A_hi, 1);   // A[lane+31] (lane>=1)
        float hi31    = __shfl_sync(FULL, A_hi, 31);     // A[63]
        if (lane == 0) prev_hi = lo31;                   // u=32 needs A[31]

        // u = lane, t = d - lane
        {
            const int t = d - lane;
            if (t >= 1 && t <= Tz - 1) {
                const float x = A_lo + s_blank[(t - 1) * BSTRIDE + lane];
                float nv;
                if (lane == 0) nv = x;
                else           nv = logadd(x, prev_lo + s_emit[t * Uz + lane - 1]);
                A_lo = nv;
                if (t == t_last && lane == tlen) final_alpha = nv;
            }
        }
        // u = lane + 32, t = d - u
        {
            const int t = d - u_hi;
            if (t >= 1 && t <= Tz - 1) {
                const float x = A_hi + s_blank[(t - 1) * BSTRIDE + u_hi];
                const float y = prev_hi + s_emit[t * Uz + u_hi - 1];
                A_hi = logadd(x, y);
                if (t == t_last && u_hi == tlen) final_alpha = A_hi;
            }
        }
        // u = 64 on lane 0
        if (lane == 0) {
            const int t = d - Uz;
            if (t >= 1 && t <= Tz - 1) {
                const float x = A_top + s_blank[(t - 1) * BSTRIDE + Uz];
                const float y = hi31 + s_emit[t * Uz + Uz - 1];
                A_top = logadd(x, y);
                if (t == t_last && Uz == tlen) final_alpha = A_top;
            }
        }
    }

    // Exactly one lane owns (t_last, tlen); have the owner write the loss.
    const bool owner = (tlen < 32)       ? (lane == tlen)
                     : (tlen < Uz)       ? (lane == tlen - 32)
                                         : (lane == 0);
    if (owner)
        g_loss[b] = -(final_alpha + s_blank[t_last * BSTRIDE + tlen]);
}

// ---------------------------------------------------------------------------
// Kernel 3: mean over batch -> scalar output.
// ---------------------------------------------------------------------------
__global__ void finish_kernel(float* __restrict__ out)
{
    if (threadIdx.x == 0) {
        float s = 0.0f;
#pragma unroll
        for (int i = 0; i < Bz; i++) s += g_loss[i];
        out[0] = s * (1.0f / Bz);
    }
}

extern "C" void kernel_launch(void* const* d_in, const int* in_sizes, int n_in,
                              void* d_out, int out_size)
{
    const float* pred       = (const float*)d_in[0];  // (B,T,U+1,V) fp32
    const int*   target     = (const int*)  d_in[1];  // (B,U)
    const int*   pred_len   = (const int*)  d_in[2];  // (B,)
    const int*   target_len = (const int*)  d_in[3];  // (B,)
    float*       out        = (float*)d_out;

    const int n_rows = Bz * Tz * U1;                  // 133120 rows
    const int blocks = (n_rows + 7) / 8;              // 8 warps / block
    lse_kernel<<<blocks, 256>>>(pred, target);

    const int smem_bytes = (Tz * BSTRIDE + Tz * Uz) * (int)sizeof(float);  // 133120 B
    cudaFuncSetAttribute(dp_kernel, cudaFuncAttributeMaxDynamicSharedMemorySize,
                         smem_bytes);
    dp_kernel<<<Bz, 256, smem_bytes>>>(pred_len, target_len);

    finish_kernel<<<1, 32>>>(out);
}

// round 4
// speedup vs baseline: 1.8150x; 1.7528x over previous
#include <cuda_runtime.h>
#include <cstddef>

#define Bz 8
#define Tz 256
#define Uz 64
#define U1 65
#define BSTRIDE 66   // padded blank row stride (odd diagonal delta -> conflict-free)
#define Vz 512

#define LOG2E 1.4426950408889634f
#define LN2   0.6931471805599453f

// Scratch (device globals: allocation inside kernel_launch is forbidden)
__device__ float g_blank[Bz * Tz * BSTRIDE];  // blank log2-prob, padded stride 66
__device__ float g_emit [Bz * Tz * Uz];       // emit  log2-prob per (b,t,u), u < U
__device__ float g_loss [Bz];

__device__ __forceinline__ float ex2f(float x) {
    float r; asm("ex2.approx.ftz.f32 %0, %1;" : "=f"(r) : "f"(x)); return r;
}
__device__ __forceinline__ float lg2f(float x) {
    float r; asm("lg2.approx.ftz.f32 %0, %1;" : "=f"(r) : "f"(x)); return r;
}

// logaddexp in log2 domain: max(x,y) + log2(1 + 2^-|x-y|)
__device__ __forceinline__ float logadd2(float x, float y)
{
    return fmaxf(x, y) + lg2f(1.0f + ex2f(-fabsf(x - y)));
}

// ---------------------------------------------------------------------------
// Kernel 1: per-row logsumexp over V=512; writes blank/emit in LOG2 domain.
// One warp per (b,t,u) row. 272 MB streamed once -> HBM-bound (81% of peak).
// ---------------------------------------------------------------------------
__global__ void __launch_bounds__(256) lse_kernel(const float* __restrict__ pred,
                                                  const int* __restrict__ target)
{
    const int warp = (blockIdx.x * blockDim.x + threadIdx.x) >> 5;
    const int lane = threadIdx.x & 31;
    const int n_rows = Bz * Tz * U1;
    if (warp >= n_rows) return;

    const float* row = pred + (size_t)warp * Vz;

    float4 v[4];
    float mx = -1e30f;
#pragma unroll
    for (int c = 0; c < 4; c++) {
        v[c] = __ldcs(reinterpret_cast<const float4*>(row + c * 128 + lane * 4));
        mx = fmaxf(mx, fmaxf(fmaxf(v[c].x, v[c].y), fmaxf(v[c].z, v[c].w)));
    }
#pragma unroll
    for (int o = 16; o > 0; o >>= 1)
        mx = fmaxf(mx, __shfl_xor_sync(0xFFFFFFFFu, mx, o));

    float s = 0.0f;
#pragma unroll
    for (int c = 0; c < 4; c++) {
        s += __expf(v[c].x - mx) + __expf(v[c].y - mx)
           + __expf(v[c].z - mx) + __expf(v[c].w - mx);
    }
#pragma unroll
    for (int o = 16; o > 0; o >>= 1)
        s += __shfl_xor_sync(0xFFFFFFFFu, s, o);

    const float lse = mx + __logf(s);

    if (lane == 0) {
        const int b   = warp / (Tz * U1);
        const int rem = warp % (Tz * U1);
        const int t   = rem / U1;
        const int u   = rem % U1;
        g_blank[(b * Tz + t) * BSTRIDE + u] = (row[0] - lse) * LOG2E;  // blank_id = 0
        if (u < Uz) {
            const int tgt = target[b * Uz + u];
            g_emit[(b * Tz + t) * Uz + u] = (row[tgt] - lse) * LOG2E;
        }
    }
}

// ---------------------------------------------------------------------------
// Kernel 2: alpha DP, anti-diagonal wavefront in a SINGLE WARP.
// BRANCH-FREE loop body: clamped SMEM indices + FSEL selects, no divergent ifs.
// Lane l owns columns u=l and u=l+32; every lane computes u=64 (broadcast),
// only lane 0 keeps it. Neighbor values travel via __shfl.
// ---------------------------------------------------------------------------
__global__ void __launch_bounds__(256) dp_kernel(const int* __restrict__ pred_len,
                                                 const int* __restrict__ target_len)
{
    const int b   = blockIdx.x;
    const int tid = threadIdx.x;

    extern __shared__ float sm[];
    float* s_blank = sm;                   // Tz * BSTRIDE floats (padded)
    float* s_emit  = sm + Tz * BSTRIDE;    // Tz * Uz floats
    __shared__ float row0s[U1];

    // Stage this batch's blank/emit from L2 into SMEM (pure float4 memcpy).
    {
        const float4* gb = reinterpret_cast<const float4*>(g_blank + b * Tz * BSTRIDE);
        float4* sb = reinterpret_cast<float4*>(s_blank);
        for (int i = tid; i < Tz * BSTRIDE / 4; i += blockDim.x) sb[i] = gb[i];
        const float4* ge = reinterpret_cast<const float4*>(g_emit + b * Tz * Uz);
        float4* se = reinterpret_cast<float4*>(s_emit);
        for (int i = tid; i < Tz * Uz / 4; i += blockDim.x) se[i] = ge[i];
    }
    __syncthreads();

    if (tid >= 32) return;                 // only warp 0 continues
    const int lane = tid;

    // Row 0: alpha2[0][u] = cumsum of emit2[0][0..u-1]
    if (lane == 0) {
        float acc = 0.0f;
        row0s[0] = 0.0f;
#pragma unroll
        for (int u = 1; u <= Uz; u++) { acc += s_emit[u - 1]; row0s[u] = acc; }
    }
    __syncwarp();

    const int t_last = pred_len[b] - 1;    // in [239, 255]
    const int tlen   = target_len[b];      // in [56, 64]

    float A_lo  = row0s[lane];             // alpha2[.][lane]
    float A_hi  = row0s[lane + 32];        // alpha2[.][lane+32]
    float A_top = row0s[Uz];               // alpha2[.][64]
    float final_alpha = 0.0f;              // t_last >= 239, always captured in-loop

    const unsigned FULL = 0xFFFFFFFFu;
    const int u_hi = lane + 32;
    const bool is0 = (lane == 0);

    // Diagonal step at which each owned column holds alpha[t_last][u]:
    const int hit_lo  = (lane == tlen)       ? t_last + lane : -1;
    const int hit_hi  = (u_hi == tlen)       ? t_last + u_hi : -1;
    const int hit_top = (Uz   == tlen && is0)? t_last + Uz   : -1;

#pragma unroll 2
    for (int d = 1; d <= (Tz - 1) + Uz; d++) {
        // Neighbor values from the END of step d-1 (read before any update).
        float prev_lo = __shfl_up_sync(FULL, A_lo, 1);   // A[lane-1]
        float lo31    = __shfl_sync(FULL, A_lo, 31);     // A[31]
        float prev_hi = __shfl_up_sync(FULL, A_hi, 1);   // A[lane+31]
        float hi31    = __shfl_sync(FULL, A_hi, 31);     // A[63]
        prev_hi = is0 ? lo31 : prev_hi;                  // u=32 neighbor is A[31]

        // ---- u = lane (0..31), t = d - lane ----
        {
            const int  t  = d - lane;
            const bool ok = (t >= 1) && (t <= Tz - 1);
            const int  tc = min(max(t, 1), Tz - 1);      // clamped, loads always run
            const float x = A_lo + s_blank[(tc - 1) * BSTRIDE + lane];
            float y = prev_lo + s_emit[tc * Uz + (lane - 1 >= 0 ? lane - 1 : 0)];
            y = is0 ? -1e30f : y;                        // u=0 has no emit path
            const float nv = logadd2(x, y);
            A_lo = ok ? nv : A_lo;
            final_alpha = (d == hit_lo) ? nv : final_alpha;
        }
        // ---- u = lane + 32 (32..63), t = d - u ----
        {
            const int  t  = d - u_hi;
            const bool ok = (t >= 1) && (t <= Tz - 1);
            const int  tc = min(max(t, 1), Tz - 1);
            const float x = A_hi + s_blank[(tc - 1) * BSTRIDE + u_hi];
            const float y = prev_hi + s_emit[tc * Uz + (u_hi - 1)];
            const float nv = logadd2(x, y);
            A_hi = ok ? nv : A_hi;
            final_alpha = (d == hit_hi) ? nv : final_alpha;
        }
        // ---- u = 64, computed by all lanes (broadcast loads), lane 0 keeps ----
        {
            const int  t  = d - Uz;
            const bool ok = (t >= 1) && (t <= Tz - 1);
            const int  tc = min(max(t, 1), Tz - 1);
            const float x = A_top + s_blank[(tc - 1) * BSTRIDE + Uz];
            const float y = hi31 + s_emit[tc * Uz + (Uz - 1)];
            const float nv = logadd2(x, y);
            A_top = ok ? nv : A_top;
            final_alpha = (d == hit_top) ? nv : final_alpha;
        }
    }

    // Exactly one lane captured final_alpha; that lane writes the loss.
    const bool owner = (tlen < 32) ? (lane == tlen)
                     : (tlen < Uz) ? (lane == tlen - 32)
                                   : is0;
    if (owner)
        g_loss[b] = -(final_alpha + s_blank[t_last * BSTRIDE + tlen]) * LN2;
}

// ---------------------------------------------------------------------------
// Kernel 3: mean over batch -> scalar output.
// ---------------------------------------------------------------------------
__global__ void finish_kernel(float* __restrict__ out)
{
    if (threadIdx.x == 0) {
        float s = 0.0f;
#pragma unroll
        for (int i = 0; i < Bz; i++) s += g_loss[i];
        out[0] = s * (1.0f / Bz);
    }
}

extern "C" void kernel_launch(void* const* d_in, const int* in_sizes, int n_in,
                              void* d_out, int out_size)
{
    const float* pred       = (const float*)d_in[0];  // (B,T,U+1,V) fp32
    const int*   target     = (const int*)  d_in[1];  // (B,U)
    const int*   pred_len   = (const int*)  d_in[2];  // (B,)
    const int*   target_len = (const int*)  d_in[3];  // (B,)
    float*       out        = (float*)d_out;

    const int n_rows = Bz * Tz * U1;                  // 133120 rows
    const int blocks = (n_rows + 7) / 8;              // 8 warps / block
    lse_kernel<<<blocks, 256>>>(pred, target);

    const int smem_bytes = (Tz * BSTRIDE + Tz * Uz) * (int)sizeof(float);  // 133120 B
    cudaFuncSetAttribute(dp_kernel, cudaFuncAttributeMaxDynamicSharedMemorySize,
                         smem_bytes);
    dp_kernel<<<Bz, 256, smem_bytes>>>(pred_len, target_len);

    finish_kernel<<<1, 32>>>(out);
}

// round 6
// speedup vs baseline: 2.0555x; 1.1325x over previous
#include <cuda_runtime.h>
#include <cstddef>

#define Bz 8
#define Tz 256
#define Uz 64
#define U1 65
#define BSTRIDE 66   // padded blank row stride (odd diagonal delta -> conflict-free)
#define Vz 512

#define LOG2E 1.4426950408889634f
#define LN2   0.6931471805599453f

// Scratch (device globals: allocation inside kernel_launch is forbidden)
__device__ float    g_blank[Bz * Tz * BSTRIDE];  // blank log2-prob, stride 66
__device__ float    g_emit [Bz * Tz * Uz];       // emit  log2-prob
__device__ float    g_loss [Bz];                 // per-batch alpha_final+blank (log2)
__device__ unsigned g_done = 0;                  // last-CTA-reduces counter

__device__ __forceinline__ float ex2f(float x) {
    float r; asm("ex2.approx.ftz.f32 %0, %1;" : "=f"(r) : "f"(x)); return r;
}

// Degree-4 minimax-ish poly for log2(1+z), z in [0,1], exact at z=0.
// max abs err ~3.5e-4 (log2) -> negligible vs 1e-3 rel-err budget.
__device__ __forceinline__ float log2_1p(float z)
{
    return z * (1.4362632f + z * (-0.6701403f + z * (0.3126861f + z * (-0.0791604f))));
}

// logaddexp in log2 domain: max(x,y) + log2(1 + 2^-|x-y|)
__device__ __forceinline__ float logadd2(float x, float y)
{
    return fmaxf(x, y) + log2_1p(ex2f(-fabsf(x - y)));
}

// ---------------------------------------------------------------------------
// Kernel 1: per-row logsumexp over V=512; writes blank/emit in LOG2 domain.
// One warp per (b,t,u) row. 272 MB streamed once -> HBM-bound (80% of peak).
// ---------------------------------------------------------------------------
__global__ void __launch_bounds__(256) lse_kernel(const float* __restrict__ pred,
                                                  const int* __restrict__ target)
{
    const int warp = (blockIdx.x * blockDim.x + threadIdx.x) >> 5;
    const int lane = threadIdx.x & 31;
    const int n_rows = Bz * Tz * U1;
    if (warp >= n_rows) return;

    const float* row = pred + (size_t)warp * Vz;

    float4 v[4];
    float mx = -1e30f;
#pragma unroll
    for (int c = 0; c < 4; c++) {
        v[c] = __ldcs(reinterpret_cast<const float4*>(row + c * 128 + lane * 4));
        mx = fmaxf(mx, fmaxf(fmaxf(v[c].x, v[c].y), fmaxf(v[c].z, v[c].w)));
    }
#pragma unroll
    for (int o = 16; o > 0; o >>= 1)
        mx = fmaxf(mx, __shfl_xor_sync(0xFFFFFFFFu, mx, o));

    float s = 0.0f;
#pragma unroll
    for (int c = 0; c < 4; c++) {
        s += __expf(v[c].x - mx) + __expf(v[c].y - mx)
           + __expf(v[c].z - mx) + __expf(v[c].w - mx);
    }
#pragma unroll
    for (int o = 16; o > 0; o >>= 1)
        s += __shfl_xor_sync(0xFFFFFFFFu, s, o);

    const float lse = mx + __logf(s);

    if (lane == 0) {
        const int b   = warp / (Tz * U1);
        const int rem = warp % (Tz * U1);
        const int t   = rem / U1;
        const int u   = rem % U1;
        g_blank[(b * Tz + t) * BSTRIDE + u] = (row[0] - lse) * LOG2E;  // blank_id = 0
        if (u < Uz) {
            const int tgt = target[b * Uz + u];
            g_emit[(b * Tz + t) * Uz + u] = (row[tgt] - lse) * LOG2E;
        }
    }
}

// ---------------------------------------------------------------------------
// Kernel 2: alpha DP, single-warp anti-diagonal wavefront, 3 phases:
//   A (d=1..64):    ramp-up, guarded, no top column, no capture
//   B (d=65..255):  steady  — all columns active: NO guards/clamps/captures,
//                   pointer-increment SMEM addressing
//   C (d=256..319): ramp-down, guarded + final-alpha capture (all hits d>=295)
// Lane l owns u=l and u=l+32; u=64 computed redundantly by all lanes.
// Final reduction fused in (last CTA sums g_loss).
// ---------------------------------------------------------------------------
__global__ void __launch_bounds__(256) dp_kernel(const int* __restrict__ pred_len,
                                                 const int* __restrict__ target_len,
                                                 float* __restrict__ out)
{
    const int b   = blockIdx.x;
    const int tid = threadIdx.x;

    extern __shared__ float sm[];
    float* s_blank = sm;                   // Tz * BSTRIDE floats (padded)
    float* s_emit  = sm + Tz * BSTRIDE;    // Tz * Uz floats
    __shared__ float row0s[U1];

    // Stage this batch's blank/emit from L2 into SMEM (pure float4 memcpy).
    {
        const float4* gb = reinterpret_cast<const float4*>(g_blank + b * Tz * BSTRIDE);
        float4* sb = reinterpret_cast<float4*>(s_blank);
        for (int i = tid; i < Tz * BSTRIDE / 4; i += blockDim.x) sb[i] = gb[i];
        const float4* ge = reinterpret_cast<const float4*>(g_emit + b * Tz * Uz);
        float4* se = reinterpret_cast<float4*>(s_emit);
        for (int i = tid; i < Tz * Uz / 4; i += blockDim.x) se[i] = ge[i];
    }
    __syncthreads();

    if (tid >= 32) return;                 // only warp 0 continues
    const int lane = tid;
    const bool is0 = (lane == 0);
    const int u_hi = lane + 32;
    const unsigned FULL = 0xFFFFFFFFu;

    // Row 0: alpha2[0][u] = cumsum of emit2[0][0..u-1]
    if (is0) {
        float acc = 0.0f;
        row0s[0] = 0.0f;
#pragma unroll
        for (int u = 1; u <= Uz; u++) { acc += s_emit[u - 1]; row0s[u] = acc; }
    }
    __syncwarp();

    const int t_last = pred_len[b] - 1;    // [239, 255]
    const int tlen   = target_len[b];      // [56, 64]

    float A_lo  = row0s[lane];
    float A_hi  = row0s[u_hi];
    float A_top = row0s[Uz];
    float final_alpha = 0.0f;              // captured in phase C (d >= 295)

    const int em_lo_off = (lane >= 1) ? lane - 1 : 0;   // clamped emit column

    // ---------------- Phase A: d = 1..64 (ramp-up, guarded) ----------------
    for (int d = 1; d <= Uz; d++) {
        float prev_lo = __shfl_up_sync(FULL, A_lo, 1);
        float lo31    = __shfl_sync(FULL, A_lo, 31);
        float prev_hi = __shfl_up_sync(FULL, A_hi, 1);
        prev_hi = is0 ? lo31 : prev_hi;

        {   // u = lane
            const int  t  = d - lane;
            const bool ok = (t >= 1);
            const int  tc = max(t, 1);
            const float x = A_lo + s_blank[(tc - 1) * BSTRIDE + lane];
            float y = prev_lo + s_emit[tc * Uz + em_lo_off];
            y = is0 ? -1e30f : y;
            const float nv = logadd2(x, y);
            A_lo = ok ? nv : A_lo;
        }
        {   // u = lane + 32
            const int  t  = d - u_hi;
            const bool ok = (t >= 1);
            const int  tc = max(t, 1);
            const float x = A_hi + s_blank[(tc - 1) * BSTRIDE + u_hi];
            const float y = prev_hi + s_emit[tc * Uz + (u_hi - 1)];
            const float nv = logadd2(x, y);
            A_hi = ok ? nv : A_hi;
        }
        // u = 64 never active for d <= 64
    }

    // ---------------- Phase B: d = 65..255 (steady, unguarded) --------------
    {
        int bl_lo  = (Uz - lane) * BSTRIDE + lane;          // (d-1-u)*66+u @ d=65
        int em_lo  = (Uz + 1 - lane) * Uz + em_lo_off;      // (d-u)*64+(u-1)
        int bl_hi  = (Uz - 32 - lane) * BSTRIDE + u_hi;
        int em_hi  = (Uz + 1 - 32 - lane) * Uz + (u_hi - 1);
        int bl_top = Uz;                                    // (65-1-64)*66+64
        int em_top = Uz + (Uz - 1);                         // 1*64+63

#pragma unroll 2
        for (int d = Uz + 1; d <= Tz - 1; d++) {
            float prev_lo = __shfl_up_sync(FULL, A_lo, 1);
            float lo31    = __shfl_sync(FULL, A_lo, 31);
            float prev_hi = __shfl_up_sync(FULL, A_hi, 1);
            float hi31    = __shfl_sync(FULL, A_hi, 31);
            prev_hi = is0 ? lo31 : prev_hi;

            const float xl = A_lo + s_blank[bl_lo];
            float       yl = prev_lo + s_emit[em_lo];
            yl = is0 ? -1e30f : yl;
            A_lo = logadd2(xl, yl);

            const float xh = A_hi + s_blank[bl_hi];
            const float yh = prev_hi + s_emit[em_hi];
            A_hi = logadd2(xh, yh);

            const float xt = A_top + s_blank[bl_top];
            const float yt = hi31 + s_emit[em_top];
            A_top = logadd2(xt, yt);

            bl_lo += BSTRIDE; em_lo += Uz;
            bl_hi += BSTRIDE; em_hi += Uz;
            bl_top += BSTRIDE; em_top += Uz;
        }
    }

    // ---------------- Phase C: d = 256..319 (ramp-down + capture) -----------
    const int hit_lo  = (lane == tlen) ? t_last + lane : -1;   // never (tlen>=56)
    const int hit_hi  = (u_hi == tlen) ? t_last + u_hi : -1;
    const int hit_top = (tlen == Uz)   ? t_last + Uz   : -1;

    for (int d = Tz; d <= Tz - 1 + Uz; d++) {
        float prev_lo = __shfl_up_sync(FULL, A_lo, 1);
        float lo31    = __shfl_sync(FULL, A_lo, 31);
        float prev_hi = __shfl_up_sync(FULL, A_hi, 1);
        float hi31    = __shfl_sync(FULL, A_hi, 31);
        prev_hi = is0 ? lo31 : prev_hi;

        {   // u = lane ; t = d-lane in [224,319] -> guard upper only
            const int  t  = d - lane;
            const bool ok = (t <= Tz - 1);
            const int  tc = min(t, Tz - 1);
            const float x = A_lo + s_blank[(tc - 1) * BSTRIDE + lane];
            float y = prev_lo + s_emit[tc * Uz + em_lo_off];
            y = is0 ? -1e30f : y;
            const float nv = logadd2(x, y);
            A_lo = ok ? nv : A_lo;
            final_alpha = (d == hit_lo) ? nv : final_alpha;
        }
        {   // u = lane+32 ; t in [160,287] -> guard upper only
            const int  t  = d - u_hi;
            const bool ok = (t <= Tz - 1);
            const int  tc = min(t, Tz - 1);
            const float x = A_hi + s_blank[(tc - 1) * BSTRIDE + u_hi];
            const float y = prev_hi + s_emit[tc * Uz + (u_hi - 1)];
            const float nv = logadd2(x, y);
            A_hi = ok ? nv : A_hi;
            final_alpha = (d == hit_hi) ? nv : final_alpha;
        }
        {   // u = 64 ; t = d-64 in [192,255] -> always valid
            const int  t = d - Uz;
            const float x = A_top + s_blank[(t - 1) * BSTRIDE + Uz];
            const float y = hi31 + s_emit[t * Uz + (Uz - 1)];
            A_top = logadd2(x, y);
            final_alpha = (d == hit_top) ? A_top : final_alpha;
        }
    }

    // Owner lane writes; last CTA to finish reduces the mean (fused finish).
    const bool owner = (tlen < 32) ? (lane == tlen)
                     : (tlen < Uz) ? (lane == tlen - 32)
                                   : is0;
    if (owner) {
        g_loss[b] = final_alpha + s_blank[t_last * BSTRIDE + tlen];  // log2 domain
        __threadfence();
        const unsigned n = atomicAdd(&g_done, 1);
        if (n == Bz - 1) {
            __threadfence();
            float s = 0.0f;
#pragma unroll
            for (int i = 0; i < Bz; i++)
                s += ((volatile float*)g_loss)[i];
            out[0] = -s * (LN2 / Bz);
            g_done = 0;                    // reset for next graph replay
        }
    }
}

extern "C" void kernel_launch(void* const* d_in, const int* in_sizes, int n_in,
                              void* d_out, int out_size)
{
    const float* pred       = (const float*)d_in[0];  // (B,T,U+1,V) fp32
    const int*   target     = (const int*)  d_in[1];  // (B,U)
    const int*   pred_len   = (const int*)  d_in[2];  // (B,)
    const int*   target_len = (const int*)  d_in[3];  // (B,)
    float*       out        = (float*)d_out;

    const int n_rows = Bz * Tz * U1;                  // 133120 rows
    const int blocks = (n_rows + 7) / 8;              // 8 warps / block
    lse_kernel<<<blocks, 256>>>(pred, target);

    const int smem_bytes = (Tz * BSTRIDE + Tz * Uz) * (int)sizeof(float);  // 133120 B
    cudaFuncSetAttribute(dp_kernel, cudaFuncAttributeMaxDynamicSharedMemorySize,
                         smem_bytes);
    dp_kernel<<<Bz, 256, smem_bytes>>>(pred_len, target_len, out);
}